// round 3
// baseline (speedup 1.0000x reference)
#include <cuda_runtime.h>
#include <math.h>

#define BB 256
#define SS 128
#define EE 512
#define HH 1024
#define VV 128
#define CC 18

// Scratch (no cudaMalloc allowed): device globals.
__device__ float g_T[VV * HH];      // T[v][h] = W_ih . emb[v] + b_ih
__device__ float g_h0[BB * HH];     // ping-pong hidden state
__device__ float g_h1[BB * HH];
__device__ float g_last[BB * HH];   // captured final hidden per batch row
__device__ float g_mlp1[BB * HH];   // relu(last @ W1^T + b1)
__device__ int   g_xin[BB * SS];    // normalized int32 token indices
__device__ int   g_len[BB];         // normalized int32 lengths

// ---------------------------------------------------------------------------
// Normalize x_in / x_lengths to int32 regardless of on-device storage dtype.
// Detection: read x_lengths[0] as int64. int64 storage -> value in [1, SS].
// int32 storage -> value = len0 + len1*2^32 >= 2^32 (len1 >= 1). Deterministic.
// ---------------------------------------------------------------------------
__global__ void __launch_bounds__(256) convert_inputs(const void* xin_raw,
                                                      const void* xlen_raw) {
    long long probe = ((const long long*)xlen_raw)[0];
    bool is64 = (probe >= 1 && probe <= SS);
    int i = blockIdx.x * blockDim.x + threadIdx.x;
    if (i < BB * SS) {
        g_xin[i] = is64 ? (int)((const long long*)xin_raw)[i]
                        : ((const int*)xin_raw)[i];
    }
    if (i < BB) {
        g_len[i] = is64 ? (int)((const long long*)xlen_raw)[i]
                        : ((const int*)xlen_raw)[i];
    }
}

__global__ void __launch_bounds__(256) zero_kernel(float* p, int n) {
    int i = blockIdx.x * blockDim.x + threadIdx.x;
    if (i < n) p[i] = 0.0f;
}

// ---------------------------------------------------------------------------
// Generic tiled GEMM: C[m][n] = act( A[m][:]·Bm[n][:] + bias[n] )
// A: [M,K] row-major, Bm: [N,K] row-major (so C = A @ Bm^T + bias)
// Tiles: BM=32, BN=64, BK=32. 128 threads, 4x4 per-thread. N bounds-checked.
// act: 0 = none, 1 = relu
// ---------------------------------------------------------------------------
__global__ void __launch_bounds__(128) gemm_bias_act(
    const float* __restrict__ A, const float* __restrict__ Bm,
    const float* __restrict__ bias, float* __restrict__ Cout,
    int M, int N, int K, int act)
{
    __shared__ float As[32][33];   // [k][m], padded
    __shared__ float Bs[32][65];   // [k][n], padded

    const int tid = threadIdx.x;
    const int tx = tid & 15;       // n-dir, TN=4 -> 64
    const int ty = tid >> 4;       // m-dir (0..7), TM=4 -> 32
    const int m0 = blockIdx.y * 32;
    const int n0 = blockIdx.x * 64;

    const int ka = tid & 31;       // load coords
    const int ra = tid >> 5;       // 0..3

    float acc[4][4] = {};

    for (int k0 = 0; k0 < K; k0 += 32) {
        #pragma unroll
        for (int r = 0; r < 8; r++) {
            int m = ra + r * 4;
            As[ka][m] = A[(size_t)(m0 + m) * K + k0 + ka];
        }
        #pragma unroll
        for (int r = 0; r < 16; r++) {
            int n = ra + r * 4;
            float v = 0.0f;
            if (n0 + n < N) v = Bm[(size_t)(n0 + n) * K + k0 + ka];
            Bs[ka][n] = v;
        }
        __syncthreads();
        #pragma unroll
        for (int kk = 0; kk < 32; kk++) {
            float a[4], b[4];
            #pragma unroll
            for (int i = 0; i < 4; i++) a[i] = As[kk][ty * 4 + i];
            #pragma unroll
            for (int j = 0; j < 4; j++) b[j] = Bs[kk][tx * 4 + j];
            #pragma unroll
            for (int i = 0; i < 4; i++)
                #pragma unroll
                for (int j = 0; j < 4; j++)
                    acc[i][j] = fmaf(a[i], b[j], acc[i][j]);
        }
        __syncthreads();
    }

    #pragma unroll
    for (int i = 0; i < 4; i++) {
        int m = m0 + ty * 4 + i;
        if (m >= M) continue;
        #pragma unroll
        for (int j = 0; j < 4; j++) {
            int n = n0 + tx * 4 + j;
            if (n >= N) continue;
            float z = acc[i][j] + bias[n];
            if (act == 1) z = fmaxf(z, 0.0f);
            Cout[(size_t)m * N + n] = z;
        }
    }
}

// ---------------------------------------------------------------------------
// One RNN step: hout[b][n] = tanh( T[g_xin[b][t]][n] + hin[b][:]·Whh[n][:] + bhh[n] )
// Capture into g_last when t == g_len[b]-1.
// Tiles: BM=32 (batch), BN=64 (hidden n), BK=32, 128 threads, 4x4 per thread.
// Register double-buffering of global tile loads. Grid: (16, 8).
// ---------------------------------------------------------------------------
__global__ void __launch_bounds__(128) rnn_step_kernel(
    const float* __restrict__ Whh, const float* __restrict__ bhh,
    const float* __restrict__ hin, float* __restrict__ hout, int t)
{
    __shared__ float As[32][33];   // [k][m]
    __shared__ float Bs[32][65];   // [k][n]

    const int tid = threadIdx.x;
    const int tx = tid & 15;
    const int ty = tid >> 4;
    const int m0 = blockIdx.y * 32;
    const int n0 = blockIdx.x * 64;

    const int ka = tid & 31;
    const int ra = tid >> 5;       // 0..3

    float pa[8], pb[16];
    // Prefetch tile 0
    #pragma unroll
    for (int r = 0; r < 8; r++)
        pa[r] = hin[(size_t)(m0 + ra + r * 4) * HH + ka];
    #pragma unroll
    for (int r = 0; r < 16; r++)
        pb[r] = Whh[(size_t)(n0 + ra + r * 4) * HH + ka];

    float acc[4][4] = {};

    for (int k0 = 0; k0 < HH; k0 += 32) {
        #pragma unroll
        for (int r = 0; r < 8; r++)  As[ka][ra + r * 4] = pa[r];
        #pragma unroll
        for (int r = 0; r < 16; r++) Bs[ka][ra + r * 4] = pb[r];
        __syncthreads();

        if (k0 + 32 < HH) {
            int kn = k0 + 32 + ka;
            #pragma unroll
            for (int r = 0; r < 8; r++)
                pa[r] = hin[(size_t)(m0 + ra + r * 4) * HH + kn];
            #pragma unroll
            for (int r = 0; r < 16; r++)
                pb[r] = Whh[(size_t)(n0 + ra + r * 4) * HH + kn];
        }

        #pragma unroll
        for (int kk = 0; kk < 32; kk++) {
            float a[4], b[4];
            #pragma unroll
            for (int i = 0; i < 4; i++) a[i] = As[kk][ty * 4 + i];
            #pragma unroll
            for (int j = 0; j < 4; j++) b[j] = Bs[kk][tx * 4 + j];
            #pragma unroll
            for (int i = 0; i < 4; i++)
                #pragma unroll
                for (int j = 0; j < 4; j++)
                    acc[i][j] = fmaf(a[i], b[j], acc[i][j]);
        }
        __syncthreads();
    }

    // Epilogue: + T[xin[m][t]][n] + bhh[n], tanh, store; capture last.
    const int c4 = (n0 >> 2) + tx;  // float4 column index
    const float4* bv4 = (const float4*)bhh;
    float4 bv = bv4[c4];

    #pragma unroll
    for (int i = 0; i < 4; i++) {
        int m = m0 + ty * 4 + i;
        int xi = g_xin[m * SS + t];
        const float4* Trow = (const float4*)(g_T + (size_t)xi * HH);
        float4 tv = Trow[c4];
        float4 a4;
        a4.x = tanhf(acc[i][0] + tv.x + bv.x);
        a4.y = tanhf(acc[i][1] + tv.y + bv.y);
        a4.z = tanhf(acc[i][2] + tv.z + bv.z);
        a4.w = tanhf(acc[i][3] + tv.w + bv.w);
        ((float4*)(hout + (size_t)m * HH))[c4] = a4;
        if (t == g_len[m] - 1)
            ((float4*)(g_last + (size_t)m * HH))[c4] = a4;
    }
}

extern "C" void kernel_launch(void* const* d_in, const int* in_sizes, int n_in,
                              void* d_out, int out_size) {
    const void*  x_in  = d_in[0];
    const void*  xlen  = d_in[1];
    const float* emb   = (const float*)d_in[2];
    const float* W_ih  = (const float*)d_in[3];
    const float* b_ih  = (const float*)d_in[4];
    const float* W_hh  = (const float*)d_in[5];
    const float* b_hh  = (const float*)d_in[6];
    const float* W1    = (const float*)d_in[7];
    const float* b1    = (const float*)d_in[8];
    const float* W2    = (const float*)d_in[9];
    const float* b2    = (const float*)d_in[10];
    float* out = (float*)d_out;

    float *Tp, *h0, *h1, *lastp, *mlp1p;
    cudaGetSymbolAddress((void**)&Tp,    g_T);
    cudaGetSymbolAddress((void**)&h0,    g_h0);
    cudaGetSymbolAddress((void**)&h1,    g_h1);
    cudaGetSymbolAddress((void**)&lastp, g_last);
    cudaGetSymbolAddress((void**)&mlp1p, g_mlp1);

    // Normalize index dtypes (int32 vs int64 storage) into device globals.
    convert_inputs<<<(BB * SS + 255) / 256, 256>>>(x_in, xlen);

    // h_0 = 0
    zero_kernel<<<(BB * HH + 255) / 256, 256>>>(h0, BB * HH);

    // T[v][h] = emb[v][:] . W_ih[h][:] + b_ih[h]   (V x H, K=E)
    gemm_bias_act<<<dim3(HH / 64, VV / 32), 128>>>(emb, W_ih, b_ih, Tp,
                                                   VV, HH, EE, 0);

    // 128 sequential RNN steps (ping-pong hidden buffers)
    for (int t = 0; t < SS; t++) {
        const float* hi = (t & 1) ? h1 : h0;
        float*       ho = (t & 1) ? h0 : h1;
        rnn_step_kernel<<<dim3(HH / 64, BB / 32), 128>>>(W_hh, b_hh, hi, ho, t);
    }

    // MLP head: mlp1 = relu(last @ W1^T + b1);  out = mlp1 @ W2^T + b2
    gemm_bias_act<<<dim3(HH / 64, BB / 32), 128>>>(lastp, W1, b1, mlp1p,
                                                   BB, HH, HH, 1);
    gemm_bias_act<<<dim3(1, BB / 32), 128>>>(mlp1p, W2, b2, out,
                                             BB, CC, HH, 0);
}

// round 4
// speedup vs baseline: 1.1810x; 1.1810x over previous
#include <cuda_runtime.h>
#include <math.h>

#define BB 256
#define SS 128
#define EE 512
#define HH 1024
#define VV 128
#define CC 18

// ---------------- device scratch (no cudaMalloc allowed) ----------------
__device__ float g_T[VV * HH];      // T[v][h] = W_ih.emb[v] + b_ih + b_hh
__device__ float g_h0[BB * HH];     // ping-pong hidden state
__device__ float g_h1[BB * HH];
__device__ float g_last[BB * HH];   // final hidden per batch row
__device__ float g_mlp1[BB * HH];   // relu(last @ W1^T + b1)
__device__ int   g_xin[BB * SS];    // normalized int32 token indices
__device__ int   g_len[BB];         // normalized int32 lengths
__device__ int          g_cnt[4];   // group-barrier arrival counters
__device__ volatile int g_sense[4]; // group-barrier sense (step-target)

// ---------------------------------------------------------------------------
// Normalize x_in / x_lengths to int32 regardless of storage dtype (int32/64).
// ---------------------------------------------------------------------------
__global__ void __launch_bounds__(256) convert_inputs(const void* xin_raw,
                                                      const void* xlen_raw) {
    long long probe = ((const long long*)xlen_raw)[0];
    bool is64 = (probe >= 1 && probe <= SS);
    int i = blockIdx.x * blockDim.x + threadIdx.x;
    if (i < BB * SS) {
        g_xin[i] = is64 ? (int)((const long long*)xin_raw)[i]
                        : ((const int*)xin_raw)[i];
    }
    if (i < BB) {
        g_len[i] = is64 ? (int)((const long long*)xlen_raw)[i]
                        : ((const int*)xlen_raw)[i];
    }
}

// ---------------------------------------------------------------------------
// Generic tiled GEMM: C[m][n] = act( A[m][:]·Bm[n][:] + bias[n] (+ bias2[n]) )
// ---------------------------------------------------------------------------
__global__ void __launch_bounds__(128) gemm_bias_act(
    const float* __restrict__ A, const float* __restrict__ Bm,
    const float* __restrict__ bias, const float* __restrict__ bias2,
    float* __restrict__ Cout, int M, int N, int K, int act)
{
    __shared__ float As[32][33];
    __shared__ float Bs[32][65];

    const int tid = threadIdx.x;
    const int tx = tid & 15;
    const int ty = tid >> 4;
    const int m0 = blockIdx.y * 32;
    const int n0 = blockIdx.x * 64;
    const int ka = tid & 31;
    const int ra = tid >> 5;

    float acc[4][4] = {};

    for (int k0 = 0; k0 < K; k0 += 32) {
        #pragma unroll
        for (int r = 0; r < 8; r++)
            As[ka][ra + r * 4] = A[(size_t)(m0 + ra + r * 4) * K + k0 + ka];
        #pragma unroll
        for (int r = 0; r < 16; r++) {
            int n = ra + r * 4;
            float v = 0.0f;
            if (n0 + n < N) v = Bm[(size_t)(n0 + n) * K + k0 + ka];
            Bs[ka][n] = v;
        }
        __syncthreads();
        #pragma unroll
        for (int kk = 0; kk < 32; kk++) {
            float a[4], b[4];
            #pragma unroll
            for (int i = 0; i < 4; i++) a[i] = As[kk][ty * 4 + i];
            #pragma unroll
            for (int j = 0; j < 4; j++) b[j] = Bs[kk][tx * 4 + j];
            #pragma unroll
            for (int i = 0; i < 4; i++)
                #pragma unroll
                for (int j = 0; j < 4; j++)
                    acc[i][j] = fmaf(a[i], b[j], acc[i][j]);
        }
        __syncthreads();
    }

    #pragma unroll
    for (int i = 0; i < 4; i++) {
        int m = m0 + ty * 4 + i;
        if (m >= M) continue;
        #pragma unroll
        for (int j = 0; j < 4; j++) {
            int n = n0 + tx * 4 + j;
            if (n >= N) continue;
            float z = acc[i][j] + bias[n];
            if (bias2) z += bias2[n];
            if (act == 1) z = fmaxf(z, 0.0f);
            Cout[(size_t)m * N + n] = z;
        }
    }
}

// ---------------------------------------------------------------------------
// Persistent RNN kernel.
// Grid: 128 CTAs = 4 batch-groups (64 rows) x 32 hidden-blocks (32 cols).
// W_hh slice resident in smem (n-pair packed, k-major). Per step:
//   stage own 64 h-rows (duplicated {h,h} float2) -> f32x2 GEMM -> tanh epilogue
//   -> per-group software barrier (self-resetting across graph replays).
// ---------------------------------------------------------------------------
#define WSTRIDE 1026                 // float2 per W row (16 rows, pad 2)
#define ASTRIDE 66                   // float2 per A row (64 k + pad 2)
#define W_ULL   (16 * WSTRIDE)       // 16416
#define ABUF_ULL (64 * ASTRIDE)      // 4224
#define SMEM_ULL (W_ULL + 2 * ABUF_ULL)
#define SMEM_BYTES (SMEM_ULL * 8)    // 198912

#define FMA2(d, a, b) \
    asm("fma.rn.f32x2 %0, %1, %2, %0;" : "+l"(d) : "l"(a), "l"(b))

__global__ void __launch_bounds__(256, 1) rnn_persistent(
    const float* __restrict__ Whh)
{
    extern __shared__ unsigned long long smu[];
    unsigned long long* Wsm   = smu;
    unsigned long long* Abuf0 = smu + W_ULL;
    unsigned long long* Abuf1 = Abuf0 + ABUF_ULL;

    const int tid = threadIdx.x;
    const int gi = blockIdx.x >> 5;   // batch group 0..3
    const int gj = blockIdx.x & 31;   // hidden block 0..31
    const int m0 = gi * 64;
    const int n0 = gj * 32;
    const int tx = tid & 15;          // n-pair lane
    const int ty = tid >> 4;          // m-group 0..15 (4 rows each)

    // ---- load resident W slice: Wsm[r2][k] = {Whh[n0+2r2][k], Whh[n0+2r2+1][k]} ----
    for (int idx = tid; idx < 32 * 1024; idx += 256) {
        int k = idx & 1023;
        int r = idx >> 10;            // local col 0..31
        float w = Whh[(size_t)(n0 + r) * HH + k];
        float* dst = (float*)(Wsm + (size_t)(r >> 1) * WSTRIDE + k);
        dst[r & 1] = w;
    }
    __syncthreads();

    // staging coords: each thread stages 16 k-values of one m-row per chunk
    const int smr = tid >> 2;         // m local 0..63
    const int sq  = tid & 3;          // k-subgroup 0..3

    int mrow[4], lenm[4];
    #pragma unroll
    for (int i = 0; i < 4; i++) {
        mrow[i] = m0 + 4 * ty + i;
        lenm[i] = g_len[mrow[i]];
    }

    const unsigned long long* wbase = Wsm + (size_t)tx * WSTRIDE;

    for (int t = 0; t < SS; t++) {
        const float* hin  = (t & 1) ? g_h1 : g_h0;
        float*       hout = (t & 1) ? g_h0 : g_h1;
        unsigned long long acc[4] = {0ull, 0ull, 0ull, 0ull};

        if (t > 0) {
            const float* gp = hin + (size_t)(m0 + smr) * HH;
            // stage chunk 0
            {
                float4* drow = (float4*)(Abuf0 + (size_t)smr * ASTRIDE);
                #pragma unroll
                for (int jj = 0; jj < 4; jj++) {
                    float4 v = __ldcg((const float4*)gp + (sq + 4 * jj));
                    drow[(sq + 4 * jj) * 2 + 0] = make_float4(v.x, v.x, v.y, v.y);
                    drow[(sq + 4 * jj) * 2 + 1] = make_float4(v.z, v.z, v.w, v.w);
                }
            }
            __syncthreads();

            for (int c = 0; c < 16; c++) {
                float4 pv[4];
                if (c + 1 < 16) {
                    #pragma unroll
                    for (int jj = 0; jj < 4; jj++)
                        pv[jj] = __ldcg((const float4*)(gp + (c + 1) * 64) + (sq + 4 * jj));
                }

                const unsigned long long* ab = (c & 1) ? Abuf1 : Abuf0;
                const unsigned long long* wk = wbase + c * 64;
                const unsigned long long* a0 = ab + (size_t)(4 * ty + 0) * ASTRIDE;
                const unsigned long long* a1 = ab + (size_t)(4 * ty + 1) * ASTRIDE;
                const unsigned long long* a2 = ab + (size_t)(4 * ty + 2) * ASTRIDE;
                const unsigned long long* a3 = ab + (size_t)(4 * ty + 3) * ASTRIDE;

                #pragma unroll 8
                for (int kk = 0; kk < 32; kk++) {
                    ulonglong2 w  = *(const ulonglong2*)(wk + 2 * kk);
                    ulonglong2 h0 = *(const ulonglong2*)(a0 + 2 * kk);
                    FMA2(acc[0], w.x, h0.x); FMA2(acc[0], w.y, h0.y);
                    ulonglong2 h1 = *(const ulonglong2*)(a1 + 2 * kk);
                    FMA2(acc[1], w.x, h1.x); FMA2(acc[1], w.y, h1.y);
                    ulonglong2 h2 = *(const ulonglong2*)(a2 + 2 * kk);
                    FMA2(acc[2], w.x, h2.x); FMA2(acc[2], w.y, h2.y);
                    ulonglong2 h3 = *(const ulonglong2*)(a3 + 2 * kk);
                    FMA2(acc[3], w.x, h3.x); FMA2(acc[3], w.y, h3.y);
                }

                if (c + 1 < 16) {
                    unsigned long long* db = ((c + 1) & 1) ? Abuf1 : Abuf0;
                    float4* drow = (float4*)(db + (size_t)smr * ASTRIDE);
                    #pragma unroll
                    for (int jj = 0; jj < 4; jj++) {
                        float4 v = pv[jj];
                        drow[(sq + 4 * jj) * 2 + 0] = make_float4(v.x, v.x, v.y, v.y);
                        drow[(sq + 4 * jj) * 2 + 1] = make_float4(v.z, v.z, v.w, v.w);
                    }
                }
                __syncthreads();
            }
        }

        // ---- epilogue: tanh(acc + T[x[b,t]][n]), write hout, capture last ----
        union { unsigned long long u; float2 f; } cv;
        #pragma unroll
        for (int i = 0; i < 4; i++) {
            cv.u = acc[i];
            int row = mrow[i];
            int xi = g_xin[row * SS + t];
            float2 tb = *(const float2*)(g_T + (size_t)xi * HH + n0 + 2 * tx);
            float2 o;
            o.x = tanhf(cv.f.x + tb.x);
            o.y = tanhf(cv.f.y + tb.y);
            *(float2*)(hout + (size_t)row * HH + n0 + 2 * tx) = o;
            if (t == lenm[i] - 1)
                *(float2*)(g_last + (size_t)row * HH + n0 + 2 * tx) = o;
        }

        // ---- per-group barrier (32 CTAs), self-resetting after 128 rounds ----
        __syncthreads();
        if (tid == 0) {
            __threadfence();                       // publish hout
            int target = (t + 1) & 127;            // t=127 -> 0 (reset state)
            int arrived = atomicAdd(&g_cnt[gi], 1);
            if (arrived == 31) {
                g_cnt[gi] = 0;
                __threadfence();
                g_sense[gi] = target;
            } else {
                while (g_sense[gi] != target) { }
                __threadfence();
            }
        }
        __syncthreads();
    }
}

extern "C" void kernel_launch(void* const* d_in, const int* in_sizes, int n_in,
                              void* d_out, int out_size) {
    const void*  x_in  = d_in[0];
    const void*  xlen  = d_in[1];
    const float* emb   = (const float*)d_in[2];
    const float* W_ih  = (const float*)d_in[3];
    const float* b_ih  = (const float*)d_in[4];
    const float* W_hh  = (const float*)d_in[5];
    const float* b_hh  = (const float*)d_in[6];
    const float* W1    = (const float*)d_in[7];
    const float* b1    = (const float*)d_in[8];
    const float* W2    = (const float*)d_in[9];
    const float* b2    = (const float*)d_in[10];
    float* out = (float*)d_out;

    float *Tp, *lastp, *mlp1p;
    cudaGetSymbolAddress((void**)&Tp,    g_T);
    cudaGetSymbolAddress((void**)&lastp, g_last);
    cudaGetSymbolAddress((void**)&mlp1p, g_mlp1);

    cudaFuncSetAttribute(rnn_persistent,
                         cudaFuncAttributeMaxDynamicSharedMemorySize, SMEM_BYTES);

    // Normalize index dtypes into device globals.
    convert_inputs<<<(BB * SS + 255) / 256, 256>>>(x_in, xlen);

    // T[v][h] = emb[v]·W_ih[h] + b_ih[h] + b_hh[h]  (fold both biases)
    gemm_bias_act<<<dim3(HH / 64, VV / 32), 128>>>(emb, W_ih, b_ih, b_hh, Tp,
                                                   VV, HH, EE, 0);

    // Persistent RNN over all 128 steps (replaces 128 launches).
    rnn_persistent<<<128, 256, SMEM_BYTES>>>(W_hh);

    // MLP head: mlp1 = relu(last @ W1^T + b1);  out = mlp1 @ W2^T + b2
    gemm_bias_act<<<dim3(HH / 64, BB / 32), 128>>>(lastp, W1, b1, nullptr, mlp1p,
                                                   BB, HH, HH, 1);
    gemm_bias_act<<<dim3(1, BB / 32), 128>>>(mlp1p, W2, b2, nullptr, out,
                                             BB, CC, HH, 0);
}

// round 5
// speedup vs baseline: 1.3791x; 1.1678x over previous
#include <cuda_runtime.h>
#include <math.h>

#define BB 256
#define SS 128
#define EE 512
#define HH 1024
#define VV 128
#define CC 18

// ---------------- device scratch (no cudaMalloc allowed) ----------------
__device__ float g_T[VV * HH];      // T[v][h] = W_ih.emb[v] + b_ih + b_hh
__device__ float g_h0[BB * HH];     // ping-pong hidden state
__device__ float g_h1[BB * HH];
__device__ float g_last[BB * HH];   // final hidden per batch row
__device__ float g_mlp1[BB * HH];   // relu(last @ W1^T + b1)
__device__ int   g_xin[BB * SS];    // normalized int32 token indices
__device__ int   g_len[BB];         // normalized int32 lengths
__device__ int          g_cnt[4];   // group-barrier arrival counters
__device__ volatile int g_sense[4]; // group-barrier sense (step-target)

// ---------------------------------------------------------------------------
// Normalize x_in / x_lengths to int32 regardless of storage dtype (int32/64).
// ---------------------------------------------------------------------------
__global__ void __launch_bounds__(256) convert_inputs(const void* xin_raw,
                                                      const void* xlen_raw) {
    long long probe = ((const long long*)xlen_raw)[0];
    bool is64 = (probe >= 1 && probe <= SS);
    int i = blockIdx.x * blockDim.x + threadIdx.x;
    if (i < BB * SS) {
        g_xin[i] = is64 ? (int)((const long long*)xin_raw)[i]
                        : ((const int*)xin_raw)[i];
    }
    if (i < BB) {
        g_len[i] = is64 ? (int)((const long long*)xlen_raw)[i]
                        : ((const int*)xlen_raw)[i];
    }
}

// ---------------------------------------------------------------------------
// Generic tiled GEMM: C[m][n] = act( A[m][:]·Bm[n][:] + bias[n] (+ bias2[n]) )
// ---------------------------------------------------------------------------
__global__ void __launch_bounds__(128) gemm_bias_act(
    const float* __restrict__ A, const float* __restrict__ Bm,
    const float* __restrict__ bias, const float* __restrict__ bias2,
    float* __restrict__ Cout, int M, int N, int K, int act)
{
    __shared__ float As[32][33];
    __shared__ float Bs[32][65];

    const int tid = threadIdx.x;
    const int tx = tid & 15;
    const int ty = tid >> 4;
    const int m0 = blockIdx.y * 32;
    const int n0 = blockIdx.x * 64;
    const int ka = tid & 31;
    const int ra = tid >> 5;

    float acc[4][4] = {};

    for (int k0 = 0; k0 < K; k0 += 32) {
        #pragma unroll
        for (int r = 0; r < 8; r++)
            As[ka][ra + r * 4] = A[(size_t)(m0 + ra + r * 4) * K + k0 + ka];
        #pragma unroll
        for (int r = 0; r < 16; r++) {
            int n = ra + r * 4;
            float v = 0.0f;
            if (n0 + n < N) v = Bm[(size_t)(n0 + n) * K + k0 + ka];
            Bs[ka][n] = v;
        }
        __syncthreads();
        #pragma unroll
        for (int kk = 0; kk < 32; kk++) {
            float a[4], b[4];
            #pragma unroll
            for (int i = 0; i < 4; i++) a[i] = As[kk][ty * 4 + i];
            #pragma unroll
            for (int j = 0; j < 4; j++) b[j] = Bs[kk][tx * 4 + j];
            #pragma unroll
            for (int i = 0; i < 4; i++)
                #pragma unroll
                for (int j = 0; j < 4; j++)
                    acc[i][j] = fmaf(a[i], b[j], acc[i][j]);
        }
        __syncthreads();
    }

    #pragma unroll
    for (int i = 0; i < 4; i++) {
        int m = m0 + ty * 4 + i;
        if (m >= M) continue;
        #pragma unroll
        for (int j = 0; j < 4; j++) {
            int n = n0 + tx * 4 + j;
            if (n >= N) continue;
            float z = acc[i][j] + bias[n];
            if (bias2) z += bias2[n];
            if (act == 1) z = fmaxf(z, 0.0f);
            Cout[(size_t)m * N + n] = z;
        }
    }
}

// ---------------------------------------------------------------------------
// Persistent RNN kernel, k-pair-packed f32x2 math.
// Grid: 128 CTAs = 4 batch-groups (64 rows) x 32 hidden-blocks (32 cols).
// W_hh slice resident in smem as [kpair][n] u64 = {W[n][2kp],W[n][2kp+1]}.
// A (h rows) staged per 32-kpair chunk as [kpair][m] u64 via register prefetch.
// Thread tile: TM=8 (m = mt+8i), TN=2 (n = 2nt, 2nt+1). 128 threads.
// acc[i][j] is f32x2 over (even-k, odd-k) partial sums; folded at epilogue.
// ---------------------------------------------------------------------------
#define WSTRIDE 34                   // u64 per W row (32 n + 2 pad)
#define ASTRIDE 67                   // u64 per A row (64 m + 3 pad)
#define W_ULL   (512 * WSTRIDE)      // 17408
#define A_ULL   (32 * ASTRIDE)       // 2144
#define SMEM_BYTES ((W_ULL + A_ULL) * 8)   // 156416

#define FMA2(d, a, b) \
    asm("fma.rn.f32x2 %0, %1, %2, %0;" : "+l"(d) : "l"(a), "l"(b))

__global__ void __launch_bounds__(128, 1) rnn_persistent(
    const float* __restrict__ Whh)
{
    extern __shared__ unsigned long long smu[];
    unsigned long long* Wsm = smu;           // [512][WSTRIDE]
    unsigned long long* Asm = smu + W_ULL;   // [32][ASTRIDE]

    const int tid = threadIdx.x;
    const int gi = blockIdx.x >> 5;   // batch group 0..3
    const int gj = blockIdx.x & 31;   // hidden block 0..31
    const int m0 = gi * 64;
    const int n0 = gj * 32;
    const int mt = tid & 7;           // m-thread 0..7
    const int nt = tid >> 3;          // n-thread 0..15

    // ---- resident W: Wsm[kp][n] = {Whh[n0+n][2kp], Whh[n0+n][2kp+1]} ----
    for (int idx = tid; idx < 512 * 32; idx += 128) {
        int kp = idx & 511;
        int n  = idx >> 9;
        float2 w = *(const float2*)(Whh + (size_t)(n0 + n) * HH + 2 * kp);
        Wsm[kp * WSTRIDE + n] = *(const unsigned long long*)&w;
    }
    __syncthreads();

    int lenm[8];
    #pragma unroll
    for (int i = 0; i < 8; i++) lenm[i] = g_len[m0 + mt + 8 * i];

    // prefetch coords: thread handles m = (tid>>4)+8j, float4 col f4 = tid&15
    const int pf_m0 = tid >> 4;       // 0..7
    const int pf_f4 = tid & 15;       // 0..15

    for (int t = 0; t < SS; t++) {
        const float* hin  = (t & 1) ? g_h1 : g_h0;
        float*       hout = (t & 1) ? g_h0 : g_h1;
        unsigned long long acc[8][2];
        #pragma unroll
        for (int i = 0; i < 8; i++) { acc[i][0] = 0ull; acc[i][1] = 0ull; }

        if (t > 0) {
            float4 pf[8];
            // prefetch chunk 0 (k floats [0,64))
            #pragma unroll
            for (int j = 0; j < 8; j++)
                pf[j] = __ldcg((const float4*)(hin + (size_t)(m0 + pf_m0 + 8 * j) * HH)
                               + pf_f4);

            for (int c = 0; c < 16; c++) {
                // store prefetched chunk into Asm[kp][m]
                #pragma unroll
                for (int j = 0; j < 8; j++) {
                    int m = pf_m0 + 8 * j;
                    float2 lo = make_float2(pf[j].x, pf[j].y);
                    float2 hi = make_float2(pf[j].z, pf[j].w);
                    Asm[(2 * pf_f4 + 0) * ASTRIDE + m] = *(const unsigned long long*)&lo;
                    Asm[(2 * pf_f4 + 1) * ASTRIDE + m] = *(const unsigned long long*)&hi;
                }
                __syncthreads();

                // prefetch next chunk (latency hidden under compute)
                if (c + 1 < 16) {
                    const float* gp = hin + (c + 1) * 64;
                    #pragma unroll
                    for (int j = 0; j < 8; j++)
                        pf[j] = __ldcg((const float4*)(gp + (size_t)(m0 + pf_m0 + 8 * j) * HH)
                                       + pf_f4);
                }

                // compute 32 kpairs of this chunk
                const unsigned long long* wrow = Wsm + (size_t)(c * 32) * WSTRIDE + 2 * nt;
                #pragma unroll 4
                for (int kp = 0; kp < 32; kp++) {
                    ulonglong2 b = *(const ulonglong2*)(wrow + (size_t)kp * WSTRIDE);
                    unsigned long long a[8];
                    #pragma unroll
                    for (int i = 0; i < 8; i++)
                        a[i] = Asm[kp * ASTRIDE + mt + 8 * i];
                    #pragma unroll
                    for (int i = 0; i < 8; i++) {
                        FMA2(acc[i][0], a[i], b.x);
                        FMA2(acc[i][1], a[i], b.y);
                    }
                }
                __syncthreads();
            }
        }

        // ---- epilogue: fold k-pair lanes, + T[x[b,t]], tanh, store ----
        union { unsigned long long u; float2 f; } cv0, cv1;
        #pragma unroll
        for (int i = 0; i < 8; i++) {
            int m = m0 + mt + 8 * i;
            int xi = g_xin[m * SS + t];
            float2 tb = *(const float2*)(g_T + (size_t)xi * HH + n0 + 2 * nt);
            cv0.u = acc[i][0];
            cv1.u = acc[i][1];
            float2 o;
            o.x = tanhf(cv0.f.x + cv0.f.y + tb.x);
            o.y = tanhf(cv1.f.x + cv1.f.y + tb.y);
            *(float2*)(hout + (size_t)m * HH + n0 + 2 * nt) = o;
            if (t == lenm[i] - 1)
                *(float2*)(g_last + (size_t)m * HH + n0 + 2 * nt) = o;
        }

        // ---- per-group barrier (32 CTAs), self-resetting after 128 rounds ----
        __syncthreads();
        if (tid == 0) {
            __threadfence();                       // publish hout
            int target = (t + 1) & 127;            // t=127 -> 0 (reset state)
            int arrived = atomicAdd(&g_cnt[gi], 1);
            if (arrived == 31) {
                g_cnt[gi] = 0;
                __threadfence();
                g_sense[gi] = target;
            } else {
                while (g_sense[gi] != target) { }
                __threadfence();
            }
        }
        __syncthreads();
    }
}

extern "C" void kernel_launch(void* const* d_in, const int* in_sizes, int n_in,
                              void* d_out, int out_size) {
    const void*  x_in  = d_in[0];
    const void*  xlen  = d_in[1];
    const float* emb   = (const float*)d_in[2];
    const float* W_ih  = (const float*)d_in[3];
    const float* b_ih  = (const float*)d_in[4];
    const float* W_hh  = (const float*)d_in[5];
    const float* b_hh  = (const float*)d_in[6];
    const float* W1    = (const float*)d_in[7];
    const float* b1    = (const float*)d_in[8];
    const float* W2    = (const float*)d_in[9];
    const float* b2    = (const float*)d_in[10];
    float* out = (float*)d_out;

    float *Tp, *lastp, *mlp1p;
    cudaGetSymbolAddress((void**)&Tp,    g_T);
    cudaGetSymbolAddress((void**)&lastp, g_last);
    cudaGetSymbolAddress((void**)&mlp1p, g_mlp1);

    cudaFuncSetAttribute(rnn_persistent,
                         cudaFuncAttributeMaxDynamicSharedMemorySize, SMEM_BYTES);

    // Normalize index dtypes into device globals.
    convert_inputs<<<(BB * SS + 255) / 256, 256>>>(x_in, xlen);

    // T[v][h] = emb[v]·W_ih[h] + b_ih[h] + b_hh[h]  (fold both biases)
    gemm_bias_act<<<dim3(HH / 64, VV / 32), 128>>>(emb, W_ih, b_ih, b_hh, Tp,
                                                   VV, HH, EE, 0);

    // Persistent RNN over all 128 steps.
    rnn_persistent<<<128, 128, SMEM_BYTES>>>(W_hh);

    // MLP head: mlp1 = relu(last @ W1^T + b1);  out = mlp1 @ W2^T + b2
    gemm_bias_act<<<dim3(HH / 64, BB / 32), 128>>>(lastp, W1, b1, nullptr, mlp1p,
                                                   BB, HH, HH, 1);
    gemm_bias_act<<<dim3(1, BB / 32), 128>>>(mlp1p, W2, b2, nullptr, out,
                                             BB, CC, HH, 0);
}